// round 16
// baseline (speedup 1.0000x reference)
#include <cuda_runtime.h>
#include <cuda_bf16.h>
#include <cstdint>
#include <cstddef>

// ---------------------------------------------------------------------------
// Problem constants
// ---------------------------------------------------------------------------
#define DIMC     512
#define NHEADS   16
#define HD       32
#define NTOK     64
#define NWIN     1024
#define MTOT     (NWIN * NTOK)      // 65536
#define QKV_COLS (3 * DIMC)         // 1536

// Scratch (device globals: allocation rules forbid cudaMalloc)
__device__ __nv_bfloat16 g_qkv [(size_t)MTOT * QKV_COLS];
__device__ __nv_bfloat16 g_att [(size_t)MTOT * DIMC];
__device__ __nv_bfloat16 g_wqkv[(size_t)QKV_COLS * DIMC];
__device__ __nv_bfloat16 g_wprj[(size_t)DIMC * DIMC];

// ---------------------------------------------------------------------------
// Helpers
// ---------------------------------------------------------------------------
__device__ __forceinline__ uint32_t smem_u32(const void* p) {
    uint32_t a;
    asm("{ .reg .u64 t; cvta.to.shared.u64 t, %1; cvt.u32.u64 %0, t; }"
        : "=r"(a) : "l"(p));
    return a;
}
#define CP_ASYNC16(dst, src) \
    asm volatile("cp.async.cg.shared.global [%0], [%1], 16;" :: "r"(dst), "l"(src))
#define CP_COMMIT() asm volatile("cp.async.commit_group;" ::: "memory")
#define CP_WAIT0()  asm volatile("cp.async.wait_group 0;" ::: "memory")
#define CP_WAIT1()  asm volatile("cp.async.wait_group 1;" ::: "memory")

#define STS128(a, x0, x1, x2, x3) \
    asm volatile("st.shared.v4.b32 [%0], {%1,%2,%3,%4};" \
        :: "r"(a), "r"(x0), "r"(x1), "r"(x2), "r"(x3) : "memory")

#define LDSM_X4(r0, r1, r2, r3, a) \
    asm volatile("ldmatrix.sync.aligned.m8n8.x4.shared.b16 {%0,%1,%2,%3}, [%4];" \
        : "=r"(r0), "=r"(r1), "=r"(r2), "=r"(r3) : "r"(a))
#define LDSM_X4T(r0, r1, r2, r3, a) \
    asm volatile("ldmatrix.sync.aligned.m8n8.x4.trans.shared.b16 {%0,%1,%2,%3}, [%4];" \
        : "=r"(r0), "=r"(r1), "=r"(r2), "=r"(r3) : "r"(a))

__device__ __forceinline__ void mma_bf16(float* c, const uint32_t* a, const uint32_t* b) {
    asm volatile(
        "mma.sync.aligned.m16n8k16.row.col.f32.bf16.bf16.f32 "
        "{%0,%1,%2,%3}, {%4,%5,%6,%7}, {%8,%9}, {%0,%1,%2,%3};"
        : "+f"(c[0]), "+f"(c[1]), "+f"(c[2]), "+f"(c[3])
        : "r"(a[0]), "r"(a[1]), "r"(a[2]), "r"(a[3]), "r"(b[0]), "r"(b[1]));
}

__device__ __forceinline__ uint32_t pk2(float x, float y) {
    __nv_bfloat162 t = __floats2bfloat162_rn(x, y);
    return *reinterpret_cast<uint32_t*>(&t);
}

// load 16 f32, convert to 16 bf16, store 32B to smem (two STS.128)
__device__ __forceinline__ void lda_f32(uint32_t dst, const float* __restrict__ src) {
    float4 f0 = *(const float4*)(src);
    float4 f1 = *(const float4*)(src + 4);
    float4 f2 = *(const float4*)(src + 8);
    float4 f3 = *(const float4*)(src + 12);
    STS128(dst,      pk2(f0.x, f0.y), pk2(f0.z, f0.w), pk2(f1.x, f1.y), pk2(f1.z, f1.w));
    STS128(dst + 16, pk2(f2.x, f2.y), pk2(f2.z, f2.w), pk2(f3.x, f3.y), pk2(f3.z, f3.w));
}

// ---------------------------------------------------------------------------
// f32 -> bf16 convert for the two weight matrices (tiny)
// ---------------------------------------------------------------------------
#define NWQ8 (QKV_COLS * DIMC / 8)       // 98304
#define NWP8 (DIMC * DIMC / 8)           // 32768
#define NCVT (NWQ8 + NWP8)

__global__ void cvt_w(const float* __restrict__ wqf, __nv_bfloat16* __restrict__ wq,
                      const float* __restrict__ wpf, __nv_bfloat16* __restrict__ wp)
{
    int i = blockIdx.x * blockDim.x + threadIdx.x;
    const float* in;
    __nv_bfloat16* out;
    if (i < NWQ8)       { in = wqf; out = wq; }
    else if (i < NCVT)  { in = wpf; out = wp; i -= NWQ8; }
    else return;
    const float4* p = (const float4*)in + 2 * (size_t)i;
    float4 a = p[0], b = p[1];
    uint4 o;
    o.x = pk2(a.x, a.y); o.y = pk2(a.z, a.w);
    o.z = pk2(b.x, b.y); o.w = pk2(b.z, b.w);
    ((uint4*)out)[i] = o;
}

// ---------------------------------------------------------------------------
// bf16 mma.sync GEMM (NT): C[M,N] = A[M,K]*B[N,K]^T + bias[N]
// R14 pipeline (measured best): 3-stage cp.async ring, ONE __syncthreads per
// iteration, prefetch of stage t+2 between the two k16 MMA blocks.
// AF32: A is f32 in global; loader converts to bf16 at the smem store
// (fuses the x-conversion pass into the QKV GEMM).
// ---------------------------------------------------------------------------
#define BM 128
#define BN 128
#define BK 32
#define NT_TILES (DIMC / BK)         // 16
#define NSTG 3
#define ROWB 144                     // bytes per padded smem row (72 bf16)
#define STG_A (BM * ROWB)            // 18432
#define STG_B (BN * ROWB)            // 18432
#define STGB  (STG_A + STG_B)        // 36864 per stage (A then B)
#define SMEM_GEMM (NSTG * STGB)      // 110592

template <bool AF32, bool OBF>
__global__ __launch_bounds__(256, 2) void gemm_bf16mma(
    const void* __restrict__ Asrc, const __nv_bfloat16* __restrict__ Bw,
    const float* __restrict__ bias, void* __restrict__ Cout, int N)
{
    extern __shared__ char smem[];
    const uint32_t sb = smem_u32(smem);
    const int tid  = threadIdx.x;
    const int lane = tid & 31;
    const int warp = tid >> 5;
    const int m0   = (warp & 3) * 32;     // warp m origin
    const int n0   = (warp >> 2) * 64;    // warp n origin
    const int bm   = blockIdx.y * BM;
    const int bn   = blockIdx.x * BN;

    // loader map: row = tid>>1 (0..127), 16 bf16 elems at (tid&1)*16
    const int lrow = tid >> 1;
    const int lgc  = (tid & 1) * 2;       // granule pair index
    const __nv_bfloat16* Agb = (const __nv_bfloat16*)Asrc
                             + (size_t)(bm + lrow) * DIMC + lgc * 8;
    const float*         Agf = (const float*)Asrc
                             + (size_t)(bm + lrow) * DIMC + lgc * 8;
    const __nv_bfloat16* Bg  = Bw + (size_t)(bn + lrow) * DIMC + lgc * 8;
    const uint32_t dA = sb + lrow * ROWB + lgc * 16;         // + stage*STGB
    const uint32_t dB = dA + STG_A;

    // prologue: stages 0,1
    #pragma unroll
    for (int st = 0; st < 2; ++st) {
        const uint32_t so = st * STGB;
        if (AF32) {
            lda_f32(dA + so, Agf + st * BK);
        } else {
            CP_ASYNC16(dA + so,      Agb + st * BK);
            CP_ASYNC16(dA + so + 16, Agb + st * BK + 8);
        }
        CP_ASYNC16(dB + so,      Bg + st * BK);
        CP_ASYNC16(dB + so + 16, Bg + st * BK + 8);
        CP_COMMIT();
    }

    float acc[2][8][4];
    #pragma unroll
    for (int mt = 0; mt < 2; ++mt)
        #pragma unroll
        for (int nt = 0; nt < 8; ++nt)
            #pragma unroll
            for (int q = 0; q < 4; ++q) acc[mt][nt][q] = 0.f;

    // ldmatrix base offsets (per lane)
    const int aRow = (lane & 15);
    const int aColB = ((lane >> 4) << 3) * 2;          // bytes
    const int bRow = (lane & 7) + ((lane >> 4) << 3);
    const int bColB = (((lane >> 3) & 1) << 3) * 2;    // bytes

    int s = 0;                        // slot of iteration t (t % 3)
    for (int t = 0; t < NT_TILES; ++t) {
        // stage t must be complete; stage t+1 may still be in flight
        if (t + 1 < NT_TILES) { CP_WAIT1(); } else { CP_WAIT0(); }
        __syncthreads();

        const uint32_t sA = sb + s * STGB;
        const uint32_t sB = sA + STG_A;

        // ---- ks = 0
        {
            uint32_t af[2][4];
            #pragma unroll
            for (int mt = 0; mt < 2; ++mt)
                LDSM_X4(af[mt][0], af[mt][1], af[mt][2], af[mt][3],
                        sA + (m0 + mt * 16 + aRow) * ROWB + aColB);
            uint32_t bf[8][2];
            #pragma unroll
            for (int np = 0; np < 4; ++np) {
                uint32_t r0, r1, r2, r3;
                LDSM_X4(r0, r1, r2, r3,
                        sB + (n0 + np * 16 + bRow) * ROWB + bColB);
                bf[2*np][0] = r0; bf[2*np][1] = r1;
                bf[2*np+1][0] = r2; bf[2*np+1][1] = r3;
            }
            #pragma unroll
            for (int mt = 0; mt < 2; ++mt)
                #pragma unroll
                for (int nt = 0; nt < 8; ++nt)
                    mma_bf16(acc[mt][nt], af[mt], bf[nt]);
        }

        // ---- prefetch stage t+2 into slot (t+2)%3 (overlaps ks=1 below)
        if (t + 2 < NT_TILES) {
            int ps = s + 2; if (ps >= NSTG) ps -= NSTG;
            const uint32_t so = ps * STGB;
            const int k0 = (t + 2) * BK;
            if (AF32) {
                lda_f32(dA + so, Agf + k0);
            } else {
                CP_ASYNC16(dA + so,      Agb + k0);
                CP_ASYNC16(dA + so + 16, Agb + k0 + 8);
            }
            CP_ASYNC16(dB + so,      Bg + k0);
            CP_ASYNC16(dB + so + 16, Bg + k0 + 8);
            CP_COMMIT();
        }

        // ---- ks = 1
        {
            const int kbB = 32;
            uint32_t af[2][4];
            #pragma unroll
            for (int mt = 0; mt < 2; ++mt)
                LDSM_X4(af[mt][0], af[mt][1], af[mt][2], af[mt][3],
                        sA + (m0 + mt * 16 + aRow) * ROWB + kbB + aColB);
            uint32_t bf[8][2];
            #pragma unroll
            for (int np = 0; np < 4; ++np) {
                uint32_t r0, r1, r2, r3;
                LDSM_X4(r0, r1, r2, r3,
                        sB + (n0 + np * 16 + bRow) * ROWB + kbB + bColB);
                bf[2*np][0] = r0; bf[2*np][1] = r1;
                bf[2*np+1][0] = r2; bf[2*np+1][1] = r3;
            }
            #pragma unroll
            for (int mt = 0; mt < 2; ++mt)
                #pragma unroll
                for (int nt = 0; nt < 8; ++nt)
                    mma_bf16(acc[mt][nt], af[mt], bf[nt]);
        }

        if (++s == NSTG) s = 0;
    }

    // epilogue
    const int erow = lane >> 2;
    const int ecol = (lane & 3) * 2;
    #pragma unroll
    for (int mt = 0; mt < 2; ++mt) {
        const int r0 = bm + m0 + mt * 16 + erow;
        #pragma unroll
        for (int nt = 0; nt < 8; ++nt) {
            const int c = bn + n0 + nt * 8 + ecol;
            const float b0 = bias[c], b1 = bias[c + 1];
            if (OBF) {
                __nv_bfloat16* C = (__nv_bfloat16*)Cout;
                *(uint32_t*)(C + (size_t)r0 * N + c) =
                    pk2(acc[mt][nt][0] + b0, acc[mt][nt][1] + b1);
                *(uint32_t*)(C + (size_t)(r0 + 8) * N + c) =
                    pk2(acc[mt][nt][2] + b0, acc[mt][nt][3] + b1);
            } else {
                float* C = (float*)Cout;
                *(float2*)(C + (size_t)r0 * N + c) =
                    make_float2(acc[mt][nt][0] + b0, acc[mt][nt][1] + b1);
                *(float2*)(C + (size_t)(r0 + 8) * N + c) =
                    make_float2(acc[mt][nt][2] + b0, acc[mt][nt][3] + b1);
            }
        }
    }
}

// ---------------------------------------------------------------------------
// Tensor-core window attention (R15: cp.async tile loads, closed-form rel
// index, __expf). One CTA = (window, head-pair). 8 warps.
// ---------------------------------------------------------------------------
#define SROW 40   // bf16 elements per smem row (80 bytes)

__global__ __launch_bounds__(256) void win_attn_mma(
    const __nv_bfloat16* __restrict__ qkv, const float* __restrict__ table,
    __nv_bfloat16* __restrict__ attout)
{
    const int blk  = blockIdx.x;
    const int b    = blk >> 3;
    const int hp   = blk & 7;
    const int tid  = threadIdx.x;
    const int lane = tid & 31;
    const int warp = tid >> 5;
    const int hh   = warp >> 2;
    const int wm   = warp & 3;
    const int h    = hp * 2 + hh;

    __shared__ __nv_bfloat16 sq[2][64 * SROW];
    __shared__ __nv_bfloat16 sk[2][64 * SROW];
    __shared__ __nv_bfloat16 sv[2][64 * SROW];
    __shared__ float tb[2][226], ts[2][226];

    // ---- async qkv tile loads: 6 x cp.async(16B) per thread
    {
        const int row = tid >> 2;
        const int seg = (tid & 3) * 8;                     // bf16 units
        const uint32_t so = row * (SROW * 2) + seg * 2;    // byte offset in tile
        #pragma unroll
        for (int e = 0; e < 2; ++e) {
            const __nv_bfloat16* gp = qkv + ((size_t)(b * 64 + row)) * QKV_COLS
                                    + (hp * 2 + e) * HD + seg;
            CP_ASYNC16(smem_u32(&sq[e][0]) + so, gp);
            CP_ASYNC16(smem_u32(&sk[e][0]) + so, gp + DIMC);
            CP_ASYNC16(smem_u32(&sv[e][0]) + so, gp + 2 * DIMC);
        }
        CP_COMMIT();
    }
    // ---- table loads (overlap the async copies): float2 head pairs
    if (tid < 225) {
        const float2 pb = *(const float2*)(table + tid * (2 * NHEADS) + hp * 2);
        const float2 ps = *(const float2*)(table + tid * (2 * NHEADS) + NHEADS + hp * 2);
        tb[0][tid] = pb.x; tb[1][tid] = pb.y;
        ts[0][tid] = ps.x; ts[1][tid] = ps.y;
    }
    CP_WAIT0();
    __syncthreads();

    const uint32_t sqb = smem_u32(&sq[hh][0]);
    const uint32_t skb = smem_u32(&sk[hh][0]);
    const uint32_t svb = smem_u32(&sv[hh][0]);

    float acc[8][4];
    #pragma unroll
    for (int nt = 0; nt < 8; ++nt)
        #pragma unroll
        for (int q = 0; q < 4; ++q) acc[nt][q] = 0.f;

    const int aRow  = lane & 15;
    const int aColB = (lane >> 4) * 16;
    const int bRow  = (lane & 7) + ((lane >> 4) << 3);
    const int bColB = ((lane >> 3) & 1) * 16;

    #pragma unroll
    for (int ks = 0; ks < 2; ++ks) {
        uint32_t af[4];
        LDSM_X4(af[0], af[1], af[2], af[3],
                sqb + (wm * 16 + aRow) * 80 + ks * 32 + aColB);
        #pragma unroll
        for (int np = 0; np < 4; ++np) {
            uint32_t r0, r1, r2, r3;
            LDSM_X4(r0, r1, r2, r3,
                    skb + (np * 16 + bRow) * 80 + ks * 32 + bColB);
            uint32_t b0[2] = {r0, r1}, b1[2] = {r2, r3};
            mma_bf16(acc[2 * np],     af, b0);
            mma_bf16(acc[2 * np + 1], af, b1);
        }
    }

    const int erow = lane >> 2;
    const int tg   = lane & 3;
    const int i0   = wm * 16 + erow;
    const int i1   = i0 + 8;
    const float qs = 0.17677669529663687f;

    // rel(i,j) = base_i - (j + 7*(j>>3));  base_i = (i>>3)*15 + (i&7) + 112
    const int base0 = (i0 >> 3) * 15 + (i0 & 7) + 112;
    const int base1 = (i1 >> 3) * 15 + (i1 & 7) + 112;

    float s0[16], s1[16];
    #pragma unroll
    for (int nt = 0; nt < 8; ++nt) {
        const int c0 = nt * 8 + 2 * tg;
        const int r0v = base0 - c0 - nt * 7;
        const int r1v = base1 - c0 - nt * 7;
        s0[2*nt]   = acc[nt][0] * qs + tb[hh][r0v];
        s0[2*nt+1] = acc[nt][1] * qs + tb[hh][r0v - 1];
        s1[2*nt]   = acc[nt][2] * qs + tb[hh][r1v];
        s1[2*nt+1] = acc[nt][3] * qs + tb[hh][r1v - 1];
    }
    float m0v = s0[0], m1v = s1[0];
    #pragma unroll
    for (int j = 1; j < 16; ++j) { m0v = fmaxf(m0v, s0[j]); m1v = fmaxf(m1v, s1[j]); }
    m0v = fmaxf(m0v, __shfl_xor_sync(0xffffffffu, m0v, 1));
    m0v = fmaxf(m0v, __shfl_xor_sync(0xffffffffu, m0v, 2));
    m1v = fmaxf(m1v, __shfl_xor_sync(0xffffffffu, m1v, 1));
    m1v = fmaxf(m1v, __shfl_xor_sync(0xffffffffu, m1v, 2));

    float sum0 = 0.f, sum1 = 0.f;
    #pragma unroll
    for (int j = 0; j < 16; ++j) {
        s0[j] = __expf(s0[j] - m0v); sum0 += s0[j];
        s1[j] = __expf(s1[j] - m1v); sum1 += s1[j];
    }
    sum0 += __shfl_xor_sync(0xffffffffu, sum0, 1);
    sum0 += __shfl_xor_sync(0xffffffffu, sum0, 2);
    sum1 += __shfl_xor_sync(0xffffffffu, sum1, 1);
    sum1 += __shfl_xor_sync(0xffffffffu, sum1, 2);
    const float inv0 = 1.f / sum0, inv1 = 1.f / sum1;

    #pragma unroll
    for (int nt = 0; nt < 8; ++nt) {
        const int c0 = nt * 8 + 2 * tg;
        const int r0v = base0 - c0 - nt * 7;
        const int r1v = base1 - c0 - nt * 7;
        s0[2*nt]   *= inv0 * ts[hh][r0v];
        s0[2*nt+1] *= inv0 * ts[hh][r0v - 1];
        s1[2*nt]   *= inv1 * ts[hh][r1v];
        s1[2*nt+1] *= inv1 * ts[hh][r1v - 1];
    }

    uint32_t pa[4][4];
    #pragma unroll
    for (int kt = 0; kt < 4; ++kt) {
        pa[kt][0] = pk2(s0[4*kt],   s0[4*kt+1]);
        pa[kt][1] = pk2(s1[4*kt],   s1[4*kt+1]);
        pa[kt][2] = pk2(s0[4*kt+2], s0[4*kt+3]);
        pa[kt][3] = pk2(s1[4*kt+2], s1[4*kt+3]);
    }

    float o[4][4];
    #pragma unroll
    for (int nt = 0; nt < 4; ++nt)
        #pragma unroll
        for (int q = 0; q < 4; ++q) o[nt][q] = 0.f;

    #pragma unroll
    for (int kt = 0; kt < 4; ++kt) {
        #pragma unroll
        for (int j = 0; j < 2; ++j) {
            uint32_t r0, r1, r2, r3;
            LDSM_X4T(r0, r1, r2, r3,
                     svb + (kt * 16 + (lane & 15)) * 80 + j * 32 + (lane >> 4) * 16);
            uint32_t b0[2] = {r0, r1}, b1[2] = {r2, r3};
            mma_bf16(o[2 * j],     pa[kt], b0);
            mma_bf16(o[2 * j + 1], pa[kt], b1);
        }
    }

    #pragma unroll
    for (int nt = 0; nt < 4; ++nt) {
        const int col = h * HD + nt * 8 + 2 * tg;
        *(uint32_t*)(attout + ((size_t)(b * 64 + i0)) * DIMC + col) =
            pk2(o[nt][0], o[nt][1]);
        *(uint32_t*)(attout + ((size_t)(b * 64 + i1)) * DIMC + col) =
            pk2(o[nt][2], o[nt][3]);
    }
}

// ---------------------------------------------------------------------------
// Launch
// ---------------------------------------------------------------------------
extern "C" void kernel_launch(void* const* d_in, const int* in_sizes, int n_in,
                              void* d_out, int out_size)
{
    const float* x      = (const float*)d_in[0];
    const float* qkv_w  = (const float*)d_in[1];
    const float* qkv_b  = (const float*)d_in[2];
    const float* proj_w = (const float*)d_in[3];
    const float* proj_b = (const float*)d_in[4];
    const float* table  = (const float*)d_in[5];
    float*       out    = (float*)d_out;

    __nv_bfloat16 *qkvb, *attb, *wq, *wp;
    cudaGetSymbolAddress((void**)&qkvb, g_qkv);
    cudaGetSymbolAddress((void**)&attb, g_att);
    cudaGetSymbolAddress((void**)&wq,   g_wqkv);
    cudaGetSymbolAddress((void**)&wp,   g_wprj);

    cudaFuncSetAttribute((const void*)gemm_bf16mma<true, true>,
        cudaFuncAttributeMaxDynamicSharedMemorySize, SMEM_GEMM);
    cudaFuncSetAttribute((const void*)gemm_bf16mma<false, false>,
        cudaFuncAttributeMaxDynamicSharedMemorySize, SMEM_GEMM);

    // 0) bf16 conversion of the two weight matrices only (x converts in-GEMM)
    cvt_w<<<(NCVT + 255) / 256, 256>>>(qkv_w, wq, proj_w, wp);

    // 1) QKV GEMM (A = f32 x, converted in the loader) -> bf16 [65536,1536]
    gemm_bf16mma<true, true><<<dim3(QKV_COLS / BN, MTOT / BM), 256, SMEM_GEMM>>>(
        x, wq, qkv_b, qkvb, QKV_COLS);

    // 2) tensor-core windowed attention (window x head-pair)
    win_attn_mma<<<NWIN * (NHEADS / 2), 256>>>(qkvb, table, attb);

    // 3) projection GEMM (A = bf16 attention output) -> f32 out
    gemm_bf16mma<false, false><<<dim3(DIMC / BN, MTOT / BM), 256, SMEM_GEMM>>>(
        attb, wp, proj_b, out, DIMC);
}

// round 17
// speedup vs baseline: 1.1893x; 1.1893x over previous
#include <cuda_runtime.h>
#include <cuda_bf16.h>
#include <cstdint>
#include <cstddef>

// ---------------------------------------------------------------------------
// Problem constants
// ---------------------------------------------------------------------------
#define DIMC     512
#define NHEADS   16
#define HD       32
#define NTOK     64
#define NWIN     1024
#define MTOT     (NWIN * NTOK)      // 65536
#define QKV_COLS (3 * DIMC)         // 1536

// Scratch (device globals: allocation rules forbid cudaMalloc)
__device__ __nv_bfloat16 g_xb  [(size_t)MTOT * DIMC];
__device__ __nv_bfloat16 g_qkv [(size_t)MTOT * QKV_COLS];
__device__ __nv_bfloat16 g_att [(size_t)MTOT * DIMC];
__device__ __nv_bfloat16 g_wqkv[(size_t)QKV_COLS * DIMC];
__device__ __nv_bfloat16 g_wprj[(size_t)DIMC * DIMC];

// ---------------------------------------------------------------------------
// Helpers
// ---------------------------------------------------------------------------
__device__ __forceinline__ uint32_t smem_u32(const void* p) {
    uint32_t a;
    asm("{ .reg .u64 t; cvta.to.shared.u64 t, %1; cvt.u32.u64 %0, t; }"
        : "=r"(a) : "l"(p));
    return a;
}
#define CP_ASYNC16(dst, src) \
    asm volatile("cp.async.cg.shared.global [%0], [%1], 16;" :: "r"(dst), "l"(src))
#define CP_COMMIT() asm volatile("cp.async.commit_group;" ::: "memory")
#define CP_WAIT0()  asm volatile("cp.async.wait_group 0;" ::: "memory")
#define CP_WAIT1()  asm volatile("cp.async.wait_group 1;" ::: "memory")

#define LDSM_X4(r0, r1, r2, r3, a) \
    asm volatile("ldmatrix.sync.aligned.m8n8.x4.shared.b16 {%0,%1,%2,%3}, [%4];" \
        : "=r"(r0), "=r"(r1), "=r"(r2), "=r"(r3) : "r"(a))
#define LDSM_X4T(r0, r1, r2, r3, a) \
    asm volatile("ldmatrix.sync.aligned.m8n8.x4.trans.shared.b16 {%0,%1,%2,%3}, [%4];" \
        : "=r"(r0), "=r"(r1), "=r"(r2), "=r"(r3) : "r"(a))

__device__ __forceinline__ void mma_bf16(float* c, const uint32_t* a, const uint32_t* b) {
    asm volatile(
        "mma.sync.aligned.m16n8k16.row.col.f32.bf16.bf16.f32 "
        "{%0,%1,%2,%3}, {%4,%5,%6,%7}, {%8,%9}, {%0,%1,%2,%3};"
        : "+f"(c[0]), "+f"(c[1]), "+f"(c[2]), "+f"(c[3])
        : "r"(a[0]), "r"(a[1]), "r"(a[2]), "r"(a[3]), "r"(b[0]), "r"(b[1]));
}

__device__ __forceinline__ uint32_t pk2(float x, float y) {
    __nv_bfloat162 t = __floats2bfloat162_rn(x, y);
    return *reinterpret_cast<uint32_t*>(&t);
}

// ---------------------------------------------------------------------------
// fused f32 -> bf16 convert for x, qkv_w, proj_w: 16 elems / thread
// (4 independent float4 loads -> MLP=4, DRAM/TLB latency fully overlapped)
// ---------------------------------------------------------------------------
#define NX16  (MTOT * DIMC / 16)          // 2097152
#define NWQ16 (QKV_COLS * DIMC / 16)      // 49152
#define NWP16 (DIMC * DIMC / 16)          // 16384
#define NCVT  (NX16 + NWQ16 + NWP16)

__global__ void cvt_all(const float* __restrict__ x, __nv_bfloat16* __restrict__ xb,
                        const float* __restrict__ wqf, __nv_bfloat16* __restrict__ wq,
                        const float* __restrict__ wpf, __nv_bfloat16* __restrict__ wp)
{
    int i = blockIdx.x * blockDim.x + threadIdx.x;
    const float* in;
    __nv_bfloat16* out;
    if (i < NX16)               { in = x;   out = xb; }
    else if (i < NX16 + NWQ16)  { in = wqf; out = wq; i -= NX16; }
    else if (i < NCVT)          { in = wpf; out = wp; i -= NX16 + NWQ16; }
    else return;
    const float4* p = (const float4*)in + 4 * (size_t)i;
    float4 a = p[0], b = p[1], c = p[2], d = p[3];
    uint4 o0, o1;
    o0.x = pk2(a.x, a.y); o0.y = pk2(a.z, a.w);
    o0.z = pk2(b.x, b.y); o0.w = pk2(b.z, b.w);
    o1.x = pk2(c.x, c.y); o1.y = pk2(c.z, c.w);
    o1.z = pk2(d.x, d.y); o1.w = pk2(d.z, d.w);
    uint4* q = (uint4*)out + 2 * (size_t)i;
    q[0] = o0;
    q[1] = o1;
}

// ---------------------------------------------------------------------------
// bf16 mma.sync GEMM (NT): C[M,N] = A[M,K]*B[N,K]^T + bias[N]
// R14/R15 (measured best): 3-stage cp.async ring, ONE __syncthreads per
// iteration, prefetch of stage t+2 issued between the two k16 MMA blocks.
// ---------------------------------------------------------------------------
#define BM 128
#define BN 128
#define BK 32
#define NT_TILES (DIMC / BK)         // 16
#define NSTG 3
#define ROWB 144                     // bytes per padded smem row (72 bf16)
#define STG_A (BM * ROWB)            // 18432
#define STG_B (BN * ROWB)            // 18432
#define STGB  (STG_A + STG_B)        // 36864 per stage (A then B)
#define SMEM_GEMM (NSTG * STGB)      // 110592

template <bool OBF>
__global__ __launch_bounds__(256, 2) void gemm_bf16mma(
    const __nv_bfloat16* __restrict__ A, const __nv_bfloat16* __restrict__ Bw,
    const float* __restrict__ bias, void* __restrict__ Cout, int N)
{
    extern __shared__ char smem[];
    const uint32_t sb = smem_u32(smem);
    const int tid  = threadIdx.x;
    const int lane = tid & 31;
    const int warp = tid >> 5;
    const int m0   = (warp & 3) * 32;     // warp m origin
    const int n0   = (warp >> 2) * 64;    // warp n origin
    const int bm   = blockIdx.y * BM;
    const int bn   = blockIdx.x * BN;

    // loader map: row = tid>>1 (0..127), 2 x 16B granules at (tid&1)*2
    const int lrow = tid >> 1;
    const int lgc  = (tid & 1) * 2;
    const __nv_bfloat16* Ag = A  + (size_t)(bm + lrow) * DIMC + lgc * 8;
    const __nv_bfloat16* Bg = Bw + (size_t)(bn + lrow) * DIMC + lgc * 8;
    const uint32_t dA = sb + lrow * ROWB + lgc * 16;         // + stage*STGB
    const uint32_t dB = dA + STG_A;

    // prologue: stages 0,1
    #pragma unroll
    for (int st = 0; st < 2; ++st) {
        const uint32_t so = st * STGB;
        CP_ASYNC16(dA + so,      Ag + st * BK);
        CP_ASYNC16(dA + so + 16, Ag + st * BK + 8);
        CP_ASYNC16(dB + so,      Bg + st * BK);
        CP_ASYNC16(dB + so + 16, Bg + st * BK + 8);
        CP_COMMIT();
    }

    float acc[2][8][4];
    #pragma unroll
    for (int mt = 0; mt < 2; ++mt)
        #pragma unroll
        for (int nt = 0; nt < 8; ++nt)
            #pragma unroll
            for (int q = 0; q < 4; ++q) acc[mt][nt][q] = 0.f;

    // ldmatrix base offsets (per lane)
    const int aRow = (lane & 15);
    const int aColB = ((lane >> 4) << 3) * 2;          // bytes
    const int bRow = (lane & 7) + ((lane >> 4) << 3);
    const int bColB = (((lane >> 3) & 1) << 3) * 2;    // bytes

    int s = 0;                        // slot of iteration t (t % 3)
    for (int t = 0; t < NT_TILES; ++t) {
        // stage t must be complete; stage t+1 may still be in flight
        if (t + 1 < NT_TILES) { CP_WAIT1(); } else { CP_WAIT0(); }
        __syncthreads();

        const uint32_t sA = sb + s * STGB;
        const uint32_t sB = sA + STG_A;

        // ---- ks = 0
        {
            uint32_t af[2][4];
            #pragma unroll
            for (int mt = 0; mt < 2; ++mt)
                LDSM_X4(af[mt][0], af[mt][1], af[mt][2], af[mt][3],
                        sA + (m0 + mt * 16 + aRow) * ROWB + aColB);
            uint32_t bf[8][2];
            #pragma unroll
            for (int np = 0; np < 4; ++np) {
                uint32_t r0, r1, r2, r3;
                LDSM_X4(r0, r1, r2, r3,
                        sB + (n0 + np * 16 + bRow) * ROWB + bColB);
                bf[2*np][0] = r0; bf[2*np][1] = r1;
                bf[2*np+1][0] = r2; bf[2*np+1][1] = r3;
            }
            #pragma unroll
            for (int mt = 0; mt < 2; ++mt)
                #pragma unroll
                for (int nt = 0; nt < 8; ++nt)
                    mma_bf16(acc[mt][nt], af[mt], bf[nt]);
        }

        // ---- prefetch stage t+2 into slot (t+2)%3 (overlaps ks=1 below)
        if (t + 2 < NT_TILES) {
            int ps = s + 2; if (ps >= NSTG) ps -= NSTG;
            const uint32_t so = ps * STGB;
            const int k0 = (t + 2) * BK;
            CP_ASYNC16(dA + so,      Ag + k0);
            CP_ASYNC16(dA + so + 16, Ag + k0 + 8);
            CP_ASYNC16(dB + so,      Bg + k0);
            CP_ASYNC16(dB + so + 16, Bg + k0 + 8);
            CP_COMMIT();
        }

        // ---- ks = 1
        {
            const int kbB = 32;
            uint32_t af[2][4];
            #pragma unroll
            for (int mt = 0; mt < 2; ++mt)
                LDSM_X4(af[mt][0], af[mt][1], af[mt][2], af[mt][3],
                        sA + (m0 + mt * 16 + aRow) * ROWB + kbB + aColB);
            uint32_t bf[8][2];
            #pragma unroll
            for (int np = 0; np < 4; ++np) {
                uint32_t r0, r1, r2, r3;
                LDSM_X4(r0, r1, r2, r3,
                        sB + (n0 + np * 16 + bRow) * ROWB + kbB + bColB);
                bf[2*np][0] = r0; bf[2*np][1] = r1;
                bf[2*np+1][0] = r2; bf[2*np+1][1] = r3;
            }
            #pragma unroll
            for (int mt = 0; mt < 2; ++mt)
                #pragma unroll
                for (int nt = 0; nt < 8; ++nt)
                    mma_bf16(acc[mt][nt], af[mt], bf[nt]);
        }

        if (++s == NSTG) s = 0;
    }

    // epilogue
    const int erow = lane >> 2;
    const int ecol = (lane & 3) * 2;
    #pragma unroll
    for (int mt = 0; mt < 2; ++mt) {
        const int r0 = bm + m0 + mt * 16 + erow;
        #pragma unroll
        for (int nt = 0; nt < 8; ++nt) {
            const int c = bn + n0 + nt * 8 + ecol;
            const float b0 = bias[c], b1 = bias[c + 1];
            if (OBF) {
                __nv_bfloat16* C = (__nv_bfloat16*)Cout;
                *(uint32_t*)(C + (size_t)r0 * N + c) =
                    pk2(acc[mt][nt][0] + b0, acc[mt][nt][1] + b1);
                *(uint32_t*)(C + (size_t)(r0 + 8) * N + c) =
                    pk2(acc[mt][nt][2] + b0, acc[mt][nt][3] + b1);
            } else {
                float* C = (float*)Cout;
                *(float2*)(C + (size_t)r0 * N + c) =
                    make_float2(acc[mt][nt][0] + b0, acc[mt][nt][1] + b1);
                *(float2*)(C + (size_t)(r0 + 8) * N + c) =
                    make_float2(acc[mt][nt][2] + b0, acc[mt][nt][3] + b1);
            }
        }
    }
}

// ---------------------------------------------------------------------------
// Tensor-core window attention (R15: cp.async tile loads, closed-form rel
// index, __expf). One CTA = (window, head-pair). 8 warps.
// ---------------------------------------------------------------------------
#define SROW 40   // bf16 elements per smem row (80 bytes)

__global__ __launch_bounds__(256) void win_attn_mma(
    const __nv_bfloat16* __restrict__ qkv, const float* __restrict__ table,
    __nv_bfloat16* __restrict__ attout)
{
    const int blk  = blockIdx.x;
    const int b    = blk >> 3;
    const int hp   = blk & 7;
    const int tid  = threadIdx.x;
    const int lane = tid & 31;
    const int warp = tid >> 5;
    const int hh   = warp >> 2;
    const int wm   = warp & 3;
    const int h    = hp * 2 + hh;

    __shared__ __nv_bfloat16 sq[2][64 * SROW];
    __shared__ __nv_bfloat16 sk[2][64 * SROW];
    __shared__ __nv_bfloat16 sv[2][64 * SROW];
    __shared__ float tb[2][226], ts[2][226];

    // ---- async qkv tile loads: 6 x cp.async(16B) per thread
    {
        const int row = tid >> 2;
        const int seg = (tid & 3) * 8;                     // bf16 units
        const uint32_t so = row * (SROW * 2) + seg * 2;    // byte offset in tile
        #pragma unroll
        for (int e = 0; e < 2; ++e) {
            const __nv_bfloat16* gp = qkv + ((size_t)(b * 64 + row)) * QKV_COLS
                                    + (hp * 2 + e) * HD + seg;
            CP_ASYNC16(smem_u32(&sq[e][0]) + so, gp);
            CP_ASYNC16(smem_u32(&sk[e][0]) + so, gp + DIMC);
            CP_ASYNC16(smem_u32(&sv[e][0]) + so, gp + 2 * DIMC);
        }
        CP_COMMIT();
    }
    // ---- table loads (overlap the async copies): float2 head pairs
    if (tid < 225) {
        const float2 pb = *(const float2*)(table + tid * (2 * NHEADS) + hp * 2);
        const float2 ps = *(const float2*)(table + tid * (2 * NHEADS) + NHEADS + hp * 2);
        tb[0][tid] = pb.x; tb[1][tid] = pb.y;
        ts[0][tid] = ps.x; ts[1][tid] = ps.y;
    }
    CP_WAIT0();
    __syncthreads();

    const uint32_t sqb = smem_u32(&sq[hh][0]);
    const uint32_t skb = smem_u32(&sk[hh][0]);
    const uint32_t svb = smem_u32(&sv[hh][0]);

    float acc[8][4];
    #pragma unroll
    for (int nt = 0; nt < 8; ++nt)
        #pragma unroll
        for (int q = 0; q < 4; ++q) acc[nt][q] = 0.f;

    const int aRow  = lane & 15;
    const int aColB = (lane >> 4) * 16;
    const int bRow  = (lane & 7) + ((lane >> 4) << 3);
    const int bColB = ((lane >> 3) & 1) * 16;

    #pragma unroll
    for (int ks = 0; ks < 2; ++ks) {
        uint32_t af[4];
        LDSM_X4(af[0], af[1], af[2], af[3],
                sqb + (wm * 16 + aRow) * 80 + ks * 32 + aColB);
        #pragma unroll
        for (int np = 0; np < 4; ++np) {
            uint32_t r0, r1, r2, r3;
            LDSM_X4(r0, r1, r2, r3,
                    skb + (np * 16 + bRow) * 80 + ks * 32 + bColB);
            uint32_t b0[2] = {r0, r1}, b1[2] = {r2, r3};
            mma_bf16(acc[2 * np],     af, b0);
            mma_bf16(acc[2 * np + 1], af, b1);
        }
    }

    const int erow = lane >> 2;
    const int tg   = lane & 3;
    const int i0   = wm * 16 + erow;
    const int i1   = i0 + 8;
    const float qs = 0.17677669529663687f;

    // rel(i,j) = base_i - (j + 7*(j>>3));  base_i = (i>>3)*15 + (i&7) + 112
    const int base0 = (i0 >> 3) * 15 + (i0 & 7) + 112;
    const int base1 = (i1 >> 3) * 15 + (i1 & 7) + 112;

    float s0[16], s1[16];
    #pragma unroll
    for (int nt = 0; nt < 8; ++nt) {
        const int c0 = nt * 8 + 2 * tg;
        const int r0v = base0 - c0 - nt * 7;
        const int r1v = base1 - c0 - nt * 7;
        s0[2*nt]   = acc[nt][0] * qs + tb[hh][r0v];
        s0[2*nt+1] = acc[nt][1] * qs + tb[hh][r0v - 1];
        s1[2*nt]   = acc[nt][2] * qs + tb[hh][r1v];
        s1[2*nt+1] = acc[nt][3] * qs + tb[hh][r1v - 1];
    }
    float m0v = s0[0], m1v = s1[0];
    #pragma unroll
    for (int j = 1; j < 16; ++j) { m0v = fmaxf(m0v, s0[j]); m1v = fmaxf(m1v, s1[j]); }
    m0v = fmaxf(m0v, __shfl_xor_sync(0xffffffffu, m0v, 1));
    m0v = fmaxf(m0v, __shfl_xor_sync(0xffffffffu, m0v, 2));
    m1v = fmaxf(m1v, __shfl_xor_sync(0xffffffffu, m1v, 1));
    m1v = fmaxf(m1v, __shfl_xor_sync(0xffffffffu, m1v, 2));

    float sum0 = 0.f, sum1 = 0.f;
    #pragma unroll
    for (int j = 0; j < 16; ++j) {
        s0[j] = __expf(s0[j] - m0v); sum0 += s0[j];
        s1[j] = __expf(s1[j] - m1v); sum1 += s1[j];
    }
    sum0 += __shfl_xor_sync(0xffffffffu, sum0, 1);
    sum0 += __shfl_xor_sync(0xffffffffu, sum0, 2);
    sum1 += __shfl_xor_sync(0xffffffffu, sum1, 1);
    sum1 += __shfl_xor_sync(0xffffffffu, sum1, 2);
    const float inv0 = 1.f / sum0, inv1 = 1.f / sum1;

    #pragma unroll
    for (int nt = 0; nt < 8; ++nt) {
        const int c0 = nt * 8 + 2 * tg;
        const int r0v = base0 - c0 - nt * 7;
        const int r1v = base1 - c0 - nt * 7;
        s0[2*nt]   *= inv0 * ts[hh][r0v];
        s0[2*nt+1] *= inv0 * ts[hh][r0v - 1];
        s1[2*nt]   *= inv1 * ts[hh][r1v];
        s1[2*nt+1] *= inv1 * ts[hh][r1v - 1];
    }

    uint32_t pa[4][4];
    #pragma unroll
    for (int kt = 0; kt < 4; ++kt) {
        pa[kt][0] = pk2(s0[4*kt],   s0[4*kt+1]);
        pa[kt][1] = pk2(s1[4*kt],   s1[4*kt+1]);
        pa[kt][2] = pk2(s0[4*kt+2], s0[4*kt+3]);
        pa[kt][3] = pk2(s1[4*kt+2], s1[4*kt+3]);
    }

    float o[4][4];
    #pragma unroll
    for (int nt = 0; nt < 4; ++nt)
        #pragma unroll
        for (int q = 0; q < 4; ++q) o[nt][q] = 0.f;

    #pragma unroll
    for (int kt = 0; kt < 4; ++kt) {
        #pragma unroll
        for (int j = 0; j < 2; ++j) {
            uint32_t r0, r1, r2, r3;
            LDSM_X4T(r0, r1, r2, r3,
                     svb + (kt * 16 + (lane & 15)) * 80 + j * 32 + (lane >> 4) * 16);
            uint32_t b0[2] = {r0, r1}, b1[2] = {r2, r3};
            mma_bf16(o[2 * j],     pa[kt], b0);
            mma_bf16(o[2 * j + 1], pa[kt], b1);
        }
    }

    #pragma unroll
    for (int nt = 0; nt < 4; ++nt) {
        const int col = h * HD + nt * 8 + 2 * tg;
        *(uint32_t*)(attout + ((size_t)(b * 64 + i0)) * DIMC + col) =
            pk2(o[nt][0], o[nt][1]);
        *(uint32_t*)(attout + ((size_t)(b * 64 + i1)) * DIMC + col) =
            pk2(o[nt][2], o[nt][3]);
    }
}

// ---------------------------------------------------------------------------
// Launch
// ---------------------------------------------------------------------------
extern "C" void kernel_launch(void* const* d_in, const int* in_sizes, int n_in,
                              void* d_out, int out_size)
{
    const float* x      = (const float*)d_in[0];
    const float* qkv_w  = (const float*)d_in[1];
    const float* qkv_b  = (const float*)d_in[2];
    const float* proj_w = (const float*)d_in[3];
    const float* proj_b = (const float*)d_in[4];
    const float* table  = (const float*)d_in[5];
    float*       out    = (float*)d_out;

    __nv_bfloat16 *xb, *qkvb, *attb, *wq, *wp;
    cudaGetSymbolAddress((void**)&xb,   g_xb);
    cudaGetSymbolAddress((void**)&qkvb, g_qkv);
    cudaGetSymbolAddress((void**)&attb, g_att);
    cudaGetSymbolAddress((void**)&wq,   g_wqkv);
    cudaGetSymbolAddress((void**)&wp,   g_wprj);

    cudaFuncSetAttribute(gemm_bf16mma<true>,
        cudaFuncAttributeMaxDynamicSharedMemorySize, SMEM_GEMM);
    cudaFuncSetAttribute(gemm_bf16mma<false>,
        cudaFuncAttributeMaxDynamicSharedMemorySize, SMEM_GEMM);

    // 0) fused bf16 conversions (x, qkv_w, proj_w), 16 elems/thread
    cvt_all<<<(NCVT + 255) / 256, 256>>>(x, xb, qkv_w, wq, proj_w, wp);

    // 1) QKV GEMM -> bf16 [65536,1536]
    gemm_bf16mma<true><<<dim3(QKV_COLS / BN, MTOT / BM), 256, SMEM_GEMM>>>(
        xb, wq, qkv_b, qkvb, QKV_COLS);

    // 2) tensor-core windowed attention (window x head-pair)
    win_attn_mma<<<NWIN * (NHEADS / 2), 256>>>(qkvb, table, attb);

    // 3) projection GEMM -> f32 out
    gemm_bf16mma<false><<<dim3(DIMC / BN, MTOT / BM), 256, SMEM_GEMM>>>(
        attb, wp, proj_b, out, DIMC);
}